// round 7
// baseline (speedup 1.0000x reference)
#include <cuda_runtime.h>
#include <math.h>

#define BB 4
#define SEQ 1024
#define DIMM 1024
#define NH 16
#define DHD 64
#define NMEM 16
#define JTOT (SEQ + NMEM)   /* 1040 */
#define ROWS (BB * SEQ)     /* 4096 */
#define QKSCALE 10.0f

// ------------------------- device scratch (no allocs) -------------------------
__device__ float g_qraw[ROWS * DIMM];
__device__ float g_kraw[ROWS * DIMM];
__device__ float g_vraw[ROWS * DIMM];
__device__ float g_vgate[ROWS * DIMM];
__device__ float g_hgate[ROWS * NH];
// pre-split tf32 hi/lo planes
__device__ float g_qh[(size_t)BB * NH * SEQ * DHD];
__device__ float g_ql[(size_t)BB * NH * SEQ * DHD];
__device__ float g_kh[(size_t)BB * NH * JTOT * DHD];
__device__ float g_kl[(size_t)BB * NH * JTOT * DHD];
__device__ float g_vh[(size_t)BB * NH * JTOT * DHD];
__device__ float g_vl[(size_t)BB * NH * JTOT * DHD];
__device__ float g_dots[(size_t)BB * NH * SEQ * JTOT];  // raw scores, then attn hi
__device__ float g_dotl[(size_t)BB * NH * SEQ * JTOT];  // attn lo plane
__device__ float g_outg[ROWS * DIMM];

// ------------------------------ tf32 helpers ---------------------------------
__device__ __forceinline__ unsigned tf32b(float x) {
    unsigned u;
    asm("cvt.rna.tf32.f32 %0, %1;" : "=r"(u) : "f"(x));
    return u;
}
__device__ __forceinline__ void tf32pair(float x, unsigned& hi, unsigned& lo) {
    hi = tf32b(x);
    lo = tf32b(x - __uint_as_float(hi));
}
__device__ __forceinline__ void mma_tf32(float c[4], const unsigned a[4], const unsigned b[2]) {
    asm volatile(
        "mma.sync.aligned.m16n8k8.row.col.f32.tf32.tf32.f32 "
        "{%0,%1,%2,%3},{%4,%5,%6,%7},{%8,%9},{%0,%1,%2,%3};\n"
        : "+f"(c[0]), "+f"(c[1]), "+f"(c[2]), "+f"(c[3])
        : "r"(a[0]), "r"(a[1]), "r"(a[2]), "r"(a[3]), "r"(b[0]), "r"(b[1]));
}
__device__ __forceinline__ void cp16(void* smem, const void* gmem) {
    unsigned s = (unsigned)__cvta_generic_to_shared(smem);
    asm volatile("cp.async.cg.shared.global [%0], [%1], 16;\n" ::"r"(s), "l"(gmem));
}
#define CP_COMMIT asm volatile("cp.async.commit_group;\n")
#define CP_WAIT(n) asm volatile("cp.async.wait_group %0;\n" ::"n"(n))

__device__ __forceinline__ float sigm(float x) { return 1.f / (1.f + __expf(-x)); }

// ------ TF32 GEMM (trunk): C = A @ B, cp.async 2-stage, cvt in loop ----------
#define APITCH 20
#define BPITCH 136
__global__ __launch_bounds__(256, 2) void tgemm_k(const float* __restrict__ A,
                                                  const float* __restrict__ Bm,
                                                  float* __restrict__ C,
                                                  int Mn, int Nn, int Kn) {
    __shared__ float As[2][128 * APITCH];
    __shared__ float Bs[2][16 * BPITCH];
    int tid = threadIdx.x;
    int row0 = blockIdx.y * 128, col0 = blockIdx.x * 128;
    int w = tid >> 5, lane = tid & 31;
    int wm = (w & 1) * 64, wn = (w >> 1) * 32;
    int qr = lane >> 2, qc = lane & 3;

    float acc[4][4][4];
#pragma unroll
    for (int i = 0; i < 4; i++)
#pragma unroll
        for (int j = 0; j < 4; j++)
#pragma unroll
            for (int u = 0; u < 4; u++) acc[i][j][u] = 0.f;

    int KT = Kn >> 4;
    {
#pragma unroll
        for (int it = 0; it < 2; it++) {
            int c = tid + it * 256;
            int ar = c >> 2, ac = (c & 3) * 4;
            cp16(&As[0][ar * APITCH + ac], &A[(size_t)(row0 + ar) * Kn + ac]);
            int br = c >> 5, bc = (c & 31) * 4;
            cp16(&Bs[0][br * BPITCH + bc], &Bm[(size_t)br * Nn + col0 + bc]);
        }
        CP_COMMIT;
    }
    for (int kt = 0; kt < KT; kt++) {
        if (kt + 1 < KT) {
            int k0 = (kt + 1) << 4;
            int st = (kt + 1) & 1;
#pragma unroll
            for (int it = 0; it < 2; it++) {
                int c = tid + it * 256;
                int ar = c >> 2, ac = (c & 3) * 4;
                cp16(&As[st][ar * APITCH + ac], &A[(size_t)(row0 + ar) * Kn + k0 + ac]);
                int br = c >> 5, bc = (c & 31) * 4;
                cp16(&Bs[st][br * BPITCH + bc], &Bm[(size_t)(k0 + br) * Nn + col0 + bc]);
            }
            CP_COMMIT;
            CP_WAIT(1);
        } else {
            CP_WAIT(0);
        }
        __syncthreads();
        const float* as = As[kt & 1];
        const float* bs = Bs[kt & 1];
#pragma unroll
        for (int ks = 0; ks < 2; ks++) {
            int k = ks * 8 + qc;
            unsigned af[4][4], bf[4][2];
#pragma unroll
            for (int mi = 0; mi < 4; mi++) {
                int m = wm + mi * 16 + qr;
                af[mi][0] = tf32b(as[m * APITCH + k]);
                af[mi][1] = tf32b(as[(m + 8) * APITCH + k]);
                af[mi][2] = tf32b(as[m * APITCH + k + 4]);
                af[mi][3] = tf32b(as[(m + 8) * APITCH + k + 4]);
            }
#pragma unroll
            for (int ni = 0; ni < 4; ni++) {
                int n = wn + ni * 8 + qr;
                bf[ni][0] = tf32b(bs[k * BPITCH + n]);
                bf[ni][1] = tf32b(bs[(k + 4) * BPITCH + n]);
            }
#pragma unroll
            for (int mi = 0; mi < 4; mi++)
#pragma unroll
                for (int ni = 0; ni < 4; ni++) mma_tf32(acc[mi][ni], af[mi], bf[ni]);
        }
        __syncthreads();
    }
#pragma unroll
    for (int mi = 0; mi < 4; mi++) {
        int r = row0 + wm + mi * 16 + qr;
#pragma unroll
        for (int ni = 0; ni < 4; ni++) {
            int c = col0 + wn + ni * 8 + 2 * qc;
            *reinterpret_cast<float2*>(&C[(size_t)r * Nn + c]) =
                make_float2(acc[mi][ni][0], acc[mi][ni][1]);
            *reinterpret_cast<float2*>(&C[(size_t)(r + 8) * Nn + c]) =
                make_float2(acc[mi][ni][2], acc[mi][ni][3]);
        }
    }
}

// ----------------- head gate logits: warp per row, 16 accums ------------------
__global__ __launch_bounds__(256) void hgate_k(const float* __restrict__ x,
                                               const float* __restrict__ W) {
    int r = (blockIdx.x * blockDim.x + threadIdx.x) >> 5;
    int lane = threadIdx.x & 31;
    const float* xr = x + (size_t)r * DIMM;
    float a[16];
#pragma unroll
    for (int h = 0; h < 16; h++) a[h] = 0.f;
    for (int d = lane; d < DIMM; d += 32) {
        float xv = xr[d];
        const float4* wr = reinterpret_cast<const float4*>(W + d * NH);
        float4 w0 = wr[0], w1 = wr[1], w2 = wr[2], w3 = wr[3];
        a[0] += xv * w0.x; a[1] += xv * w0.y; a[2] += xv * w0.z; a[3] += xv * w0.w;
        a[4] += xv * w1.x; a[5] += xv * w1.y; a[6] += xv * w1.z; a[7] += xv * w1.w;
        a[8] += xv * w2.x; a[9] += xv * w2.y; a[10] += xv * w2.z; a[11] += xv * w2.w;
        a[12] += xv * w3.x; a[13] += xv * w3.y; a[14] += xv * w3.z; a[15] += xv * w3.w;
    }
#pragma unroll
    for (int h = 0; h < 16; h++)
#pragma unroll
        for (int o = 16; o; o >>= 1) a[h] += __shfl_xor_sync(0xffffffffu, a[h], o);
    if (lane == 0) {
        float4* dst = reinterpret_cast<float4*>(&g_hgate[r * NH]);
        dst[0] = make_float4(a[0], a[1], a[2], a[3]);
        dst[1] = make_float4(a[4], a[5], a[6], a[7]);
        dst[2] = make_float4(a[8], a[9], a[10], a[11]);
        dst[3] = make_float4(a[12], a[13], a[14], a[15]);
    }
}

// -- l2norm + scale + RoPE for q,k; v copy — all written as tf32 hi/lo planes --
__global__ __launch_bounds__(256) void normrope_k(const float* __restrict__ freqs,
                                                  const float* __restrict__ q_scale,
                                                  const float* __restrict__ k_scale) {
    int gw = (blockIdx.x * blockDim.x + threadIdx.x) >> 5;
    int lane = threadIdx.x & 31;
    int row = gw / NH, h = gw - row * NH;
    int b = row / SEQ, n = row - b * SEQ;
    int d0 = lane * 2;
    size_t src = (size_t)row * DIMM + h * DHD + d0;
    float f = freqs[n * DHD + d0];
    float sf, cf;
    sincosf(f, &sf, &cf);
    unsigned h0, l0, h1, l1;
    {   // q
        float x0 = g_qraw[src], x1 = g_qraw[src + 1];
        float ss = x0 * x0 + x1 * x1;
#pragma unroll
        for (int o = 16; o; o >>= 1) ss += __shfl_xor_sync(0xffffffffu, ss, o);
        float inv = 1.f / fmaxf(sqrtf(ss), 1e-12f);
        x0 = x0 * inv * q_scale[h * DHD + d0];
        x1 = x1 * inv * q_scale[h * DHD + d0 + 1];
        float r0 = x0 * cf - x1 * sf;
        float r1 = x1 * cf + x0 * sf;
        size_t dst = ((size_t)(b * NH + h) * SEQ + n) * DHD + d0;
        tf32pair(r0, h0, l0);
        tf32pair(r1, h1, l1);
        g_qh[dst] = __uint_as_float(h0); g_qh[dst + 1] = __uint_as_float(h1);
        g_ql[dst] = __uint_as_float(l0); g_ql[dst + 1] = __uint_as_float(l1);
    }
    {   // k
        float x0 = g_kraw[src], x1 = g_kraw[src + 1];
        float ss = x0 * x0 + x1 * x1;
#pragma unroll
        for (int o = 16; o; o >>= 1) ss += __shfl_xor_sync(0xffffffffu, ss, o);
        float inv = 1.f / fmaxf(sqrtf(ss), 1e-12f);
        x0 = x0 * inv * k_scale[h * DHD + d0];
        x1 = x1 * inv * k_scale[h * DHD + d0 + 1];
        float r0 = x0 * cf - x1 * sf;
        float r1 = x1 * cf + x0 * sf;
        size_t dst = ((size_t)(b * NH + h) * JTOT + NMEM + n) * DHD + d0;
        tf32pair(r0, h0, l0);
        tf32pair(r1, h1, l1);
        g_kh[dst] = __uint_as_float(h0); g_kh[dst + 1] = __uint_as_float(h1);
        g_kl[dst] = __uint_as_float(l0); g_kl[dst + 1] = __uint_as_float(l1);
    }
    {   // v
        float v0 = g_vraw[src], v1 = g_vraw[src + 1];
        size_t dst = ((size_t)(b * NH + h) * JTOT + NMEM + n) * DHD + d0;
        tf32pair(v0, h0, l0);
        tf32pair(v1, h1, l1);
        g_vh[dst] = __uint_as_float(h0); g_vh[dst + 1] = __uint_as_float(h1);
        g_vl[dst] = __uint_as_float(l0); g_vl[dst + 1] = __uint_as_float(l1);
    }
}

// ------------- memory kv slots: l2norm(mem_k)*k_scale, copy mem_v -------------
__global__ __launch_bounds__(256) void memprep_k(const float* __restrict__ mem_k,
                                                 const float* __restrict__ mem_v,
                                                 const float* __restrict__ k_scale) {
    int gw = (blockIdx.x * blockDim.x + threadIdx.x) >> 5;
    int lane = threadIdx.x & 31;
    int h = gw / NMEM, m = gw - h * NMEM;
    int d0 = lane * 2;
    float x0 = mem_k[(h * NMEM + m) * DHD + d0];
    float x1 = mem_k[(h * NMEM + m) * DHD + d0 + 1];
    float ss = x0 * x0 + x1 * x1;
#pragma unroll
    for (int o = 16; o; o >>= 1) ss += __shfl_xor_sync(0xffffffffu, ss, o);
    float inv = 1.f / fmaxf(sqrtf(ss), 1e-12f);
    x0 = x0 * inv * k_scale[h * DHD + d0];
    x1 = x1 * inv * k_scale[h * DHD + d0 + 1];
    float v0 = mem_v[(h * NMEM + m) * DHD + d0];
    float v1 = mem_v[(h * NMEM + m) * DHD + d0 + 1];
    unsigned kh0, kl0, kh1, kl1, vh0, vl0, vh1, vl1;
    tf32pair(x0, kh0, kl0); tf32pair(x1, kh1, kl1);
    tf32pair(v0, vh0, vl0); tf32pair(v1, vh1, vl1);
    for (int b = 0; b < BB; b++) {
        size_t dst = ((size_t)(b * NH + h) * JTOT + m) * DHD + d0;
        g_kh[dst] = __uint_as_float(kh0); g_kh[dst + 1] = __uint_as_float(kh1);
        g_kl[dst] = __uint_as_float(kl0); g_kl[dst + 1] = __uint_as_float(kl1);
        g_vh[dst] = __uint_as_float(vh0); g_vh[dst + 1] = __uint_as_float(vh1);
        g_vl[dst] = __uint_as_float(vl0); g_vl[dst + 1] = __uint_as_float(vl1);
    }
}

// --- dots = QKSCALE * q.k: 3xTF32 mma, planes pre-split in global, cp.async ---
#define DQP 68
__global__ __launch_bounds__(256) void dots_k() {
    int i0 = blockIdx.y * 64;
    int j0 = blockIdx.x * 64;
    if (j0 > i0 + 63 + NMEM) return;
    extern __shared__ float dsm[];
    float* Qh = dsm;
    float* Ql = Qh + 64 * DQP;
    float* Kh = Ql + 64 * DQP;
    float* Kl = Kh + 64 * DQP;
    int bh = blockIdx.z;
    const float* QH = g_qh + (size_t)bh * SEQ * DHD;
    const float* QL = g_ql + (size_t)bh * SEQ * DHD;
    const float* KH = g_kh + (size_t)bh * JTOT * DHD;
    const float* KL = g_kl + (size_t)bh * JTOT * DHD;
    int tid = threadIdx.x;
#pragma unroll
    for (int it = 0; it < 4; it++) {
        int c = tid + it * 256;
        int r = c >> 4, d4 = (c & 15) * 4;
        cp16(&Qh[r * DQP + d4], &QH[(size_t)(i0 + r) * DHD + d4]);
        cp16(&Ql[r * DQP + d4], &QL[(size_t)(i0 + r) * DHD + d4]);
        int jj = j0 + r;
        if (jj < JTOT) {
            cp16(&Kh[r * DQP + d4], &KH[(size_t)jj * DHD + d4]);
            cp16(&Kl[r * DQP + d4], &KL[(size_t)jj * DHD + d4]);
        } else {
            *reinterpret_cast<float4*>(&Kh[r * DQP + d4]) = make_float4(0.f, 0.f, 0.f, 0.f);
            *reinterpret_cast<float4*>(&Kl[r * DQP + d4]) = make_float4(0.f, 0.f, 0.f, 0.f);
        }
    }
    CP_COMMIT;
    CP_WAIT(0);
    __syncthreads();
    int w = tid >> 5, lane = tid & 31;
    int wm = (w >> 1) * 16, wn = (w & 1) * 32;
    int qr = lane >> 2, qc = lane & 3;
    float acc[4][4] = {};
#pragma unroll
    for (int kk = 0; kk < 8; kk++) {
        int k = kk * 8 + qc;
        unsigned ah[4], al[4];
        ah[0] = __float_as_uint(Qh[(wm + qr) * DQP + k]);
        ah[1] = __float_as_uint(Qh[(wm + qr + 8) * DQP + k]);
        ah[2] = __float_as_uint(Qh[(wm + qr) * DQP + k + 4]);
        ah[3] = __float_as_uint(Qh[(wm + qr + 8) * DQP + k + 4]);
        al[0] = __float_as_uint(Ql[(wm + qr) * DQP + k]);
        al[1] = __float_as_uint(Ql[(wm + qr + 8) * DQP + k]);
        al[2] = __float_as_uint(Ql[(wm + qr) * DQP + k + 4]);
        al[3] = __float_as_uint(Ql[(wm + qr + 8) * DQP + k + 4]);
#pragma unroll
        for (int ni = 0; ni < 4; ni++) {
            int n = wn + ni * 8 + qr;
            unsigned bh2[2], bl2[2];
            bh2[0] = __float_as_uint(Kh[n * DQP + k]);
            bh2[1] = __float_as_uint(Kh[n * DQP + k + 4]);
            bl2[0] = __float_as_uint(Kl[n * DQP + k]);
            bl2[1] = __float_as_uint(Kl[n * DQP + k + 4]);
            mma_tf32(acc[ni], ah, bh2);
            mma_tf32(acc[ni], ah, bl2);
            mma_tf32(acc[ni], al, bh2);
        }
    }
    float* D = g_dots + (size_t)bh * SEQ * JTOT;
#pragma unroll
    for (int ni = 0; ni < 4; ni++) {
        int i = i0 + wm + qr;
        int j = j0 + wn + ni * 8 + 2 * qc;
        if (j < JTOT) {
            *reinterpret_cast<float2*>(&D[(size_t)i * JTOT + j]) =
                make_float2(acc[ni][0] * QKSCALE, acc[ni][1] * QKSCALE);
            *reinterpret_cast<float2*>(&D[(size_t)(i + 8) * JTOT + j]) =
                make_float2(acc[ni][2] * QKSCALE, acc[ni][3] * QKSCALE);
        }
    }
}

// -- pre-mix + causal softmax + post-mix; writes attn hi/lo planes + band zeros
__global__ __launch_bounds__(256) void mixsoft_k(const float* __restrict__ W_pre,
                                                 const float* __restrict__ W_post) {
    extern __shared__ float S[];  // NH * JTOT
    __shared__ float wpre[NH * NH], wpost[NH * NH], inv_l[NH];
    int i = SEQ - 1 - (int)blockIdx.x;  // largest jcnt first
    int b = blockIdx.y;
    int tid = threadIdx.x;
    wpre[tid] = W_pre[tid];
    wpost[tid] = W_post[tid];
    int jcnt = i + NMEM + 1;
    size_t base = ((size_t)(b * NH) * SEQ + i) * JTOT;
    for (int h = 0; h < NH; h++) {
        size_t off = base + (size_t)h * SEQ * JTOT;
        for (int j = tid; j < jcnt; j += 256) S[h * JTOT + j] = g_dots[off + j];
    }
    __syncthreads();
    for (int j = tid; j < jcnt; j += 256) {
        float sv[NH];
#pragma unroll
        for (int h = 0; h < NH; h++) sv[h] = S[h * JTOT + j];
#pragma unroll
        for (int g = 0; g < NH; g++) {
            float a = 0.f;
#pragma unroll
            for (int h = 0; h < NH; h++) a += wpre[g * NH + h] * sv[h];
            S[g * JTOT + j] = a;
        }
    }
    __syncthreads();
    int w = tid >> 5, lane = tid & 31;
    for (int g = w; g < NH; g += 8) {
        float mx = -3.0e38f;
        for (int j = lane; j < jcnt; j += 32) mx = fmaxf(mx, S[g * JTOT + j]);
#pragma unroll
        for (int o = 16; o; o >>= 1) mx = fmaxf(mx, __shfl_xor_sync(0xffffffffu, mx, o));
        float sum = 0.f;
        for (int j = lane; j < jcnt; j += 32) {
            float e = __expf(S[g * JTOT + j] - mx);
            S[g * JTOT + j] = e;
            sum += e;
        }
#pragma unroll
        for (int o = 16; o; o >>= 1) sum += __shfl_xor_sync(0xffffffffu, sum, o);
        if (lane == 0) inv_l[g] = 1.f / sum;
    }
    __syncthreads();
    for (int j = tid; j < jcnt; j += 256) {
        float pv[NH];
#pragma unroll
        for (int h = 0; h < NH; h++) pv[h] = S[h * JTOT + j] * inv_l[h];
#pragma unroll
        for (int g = 0; g < NH; g++) {
            float a = 0.f;
#pragma unroll
            for (int h = 0; h < NH; h++) a += wpost[g * NH + h] * pv[h];
            unsigned hi, lo;
            tf32pair(a, hi, lo);
            size_t o = base + (size_t)g * SEQ * JTOT + j;
            g_dots[o] = __uint_as_float(hi);
            g_dotl[o] = __uint_as_float(lo);
        }
    }
    // zero only the band outgemm will read: [jcnt, (i&~63)+80), both planes
    int zend = (i & ~63) + 80;
    if (zend > JTOT) zend = JTOT;
    for (int j = jcnt + tid; j < zend; j += 256) {
#pragma unroll
        for (int g = 0; g < NH; g++) {
            size_t o = base + (size_t)g * SEQ * JTOT + j;
            g_dots[o] = 0.f;
            g_dotl[o] = 0.f;
        }
    }
}

// ---- out = attn @ v: 3xTF32 mma, all planes pre-split in global + gates ------
#define OPITCH 20
#define VPITCH 17
__global__ __launch_bounds__(256) void outgemm_k(const float* __restrict__ b_h,
                                                 const float* __restrict__ b_v,
                                                 float* __restrict__ outg) {
    __shared__ float Ah[64 * OPITCH];
    __shared__ float Al[64 * OPITCH];
    __shared__ float Vh[64 * VPITCH];
    __shared__ float Vl[64 * VPITCH];
    int bg = blockIdx.y;
    int b = bg >> 4, g = bg & 15;
    int i0 = blockIdx.x * 64;
    const float* AH = g_dots + (size_t)bg * SEQ * JTOT;
    const float* AL = g_dotl + (size_t)bg * SEQ * JTOT;
    const float* VH = g_vh + (size_t)bg * JTOT * DHD;
    const float* VL = g_vl + (size_t)bg * JTOT * DHD;
    int tid = threadIdx.x;
    int w = tid >> 5, lane = tid & 31;
    int wm = (w >> 1) * 16, wn = (w & 1) * 32;
    int qr = lane >> 2, qc = lane & 3;
    float acc[4][4] = {};
    int kmax = i0 + 80;
    if (kmax > JTOT) kmax = JTOT;
    for (int k0 = 0; k0 < kmax; k0 += 16) {
        {
            int r = tid >> 2, c4 = (tid & 3) * 4;
            cp16(&Ah[r * OPITCH + c4], &AH[(size_t)(i0 + r) * JTOT + k0 + c4]);
            cp16(&Al[r * OPITCH + c4], &AL[(size_t)(i0 + r) * JTOT + k0 + c4]);
        }
        {
            int kk = tid >> 4, d4 = (tid & 15) * 4;
            float4 vh = *reinterpret_cast<const float4*>(&VH[(size_t)(k0 + kk) * DHD + d4]);
            float4 vl = *reinterpret_cast<const float4*>(&VL[(size_t)(k0 + kk) * DHD + d4]);
            Vh[(d4 + 0) * VPITCH + kk] = vh.x;
            Vh[(d4 + 1) * VPITCH + kk] = vh.y;
            Vh[(d4 + 2) * VPITCH + kk] = vh.z;
            Vh[(d4 + 3) * VPITCH + kk] = vh.w;
            Vl[(d4 + 0) * VPITCH + kk] = vl.x;
            Vl[(d4 + 1) * VPITCH + kk] = vl.y;
            Vl[(d4 + 2) * VPITCH + kk] = vl.z;
            Vl[(d4 + 3) * VPITCH + kk] = vl.w;
        }
        CP_COMMIT;
        CP_WAIT(0);
        __syncthreads();
#pragma unroll
        for (int ks = 0; ks < 2; ks++) {
            int k = ks * 8 + qc;
            unsigned ah[4], al[4];
            ah[0] = __float_as_uint(Ah[(wm + qr) * OPITCH + k]);
            ah[1] = __float_as_uint(Ah[(wm + qr + 8) * OPITCH + k]);
            ah[2] = __float_as_uint(Ah[(wm + qr) * OPITCH + k + 4]);
            ah[3] = __float_as_uint(Ah[(wm + qr + 8) * OPITCH + k + 4]);
            al[0] = __float_as_uint(Al[(wm + qr) * OPITCH + k]);
            al[1] = __float_as_uint(Al[(wm + qr + 8) * OPITCH + k]);
            al[2] = __float_as_uint(Al[(wm + qr) * OPITCH + k + 4]);
            al[3] = __float_as_uint(Al[(wm + qr + 8) * OPITCH + k + 4]);
#pragma unroll
            for (int ni = 0; ni < 4; ni++) {
                int n = wn + ni * 8 + qr;
                unsigned bh2[2], bl2[2];
                bh2[0] = __float_as_uint(Vh[n * VPITCH + k]);
                bh2[1] = __float_as_uint(Vh[n * VPITCH + k + 4]);
                bl2[0] = __float_as_uint(Vl[n * VPITCH + k]);
                bl2[1] = __float_as_uint(Vl[n * VPITCH + k + 4]);
                mma_tf32(acc[ni], ah, bh2);
                mma_tf32(acc[ni], ah, bl2);
                mma_tf32(acc[ni], al, bh2);
            }
        }
        __syncthreads();
    }
#pragma unroll
    for (int rr = 0; rr < 2; rr++) {
        int i = i0 + wm + qr + rr * 8;
        int r = b * SEQ + i;
        float hg = sigm(g_hgate[r * NH + g] + b_h[g]);
#pragma unroll
        for (int ni = 0; ni < 4; ni++) {
            int c = g * DHD + wn + ni * 8 + 2 * qc;
            float2 vgl = *reinterpret_cast<const float2*>(&g_vgate[(size_t)r * DIMM + c]);
            float2 bvl = *reinterpret_cast<const float2*>(&b_v[c]);
            float o0 = acc[ni][rr * 2 + 0] * hg * sigm(vgl.x + bvl.x);
            float o1 = acc[ni][rr * 2 + 1] * hg * sigm(vgl.y + bvl.y);
            *reinterpret_cast<float2*>(&outg[(size_t)r * DIMM + c]) = make_float2(o0, o1);
        }
    }
}

// ------------------------------------------------------------------------------
extern "C" void kernel_launch(void* const* d_in, const int* in_sizes, int n_in,
                              void* d_out, int out_size) {
    const float* x       = (const float*)d_in[0];
    const float* freqs   = (const float*)d_in[1];
    const float* Wq      = (const float*)d_in[2];
    const float* Wk      = (const float*)d_in[3];
    const float* Wv      = (const float*)d_in[4];
    const float* q_scale = (const float*)d_in[5];
    const float* k_scale = (const float*)d_in[6];
    const float* mem_k   = (const float*)d_in[7];
    const float* mem_v   = (const float*)d_in[8];
    const float* W_pre   = (const float*)d_in[9];
    const float* W_post  = (const float*)d_in[10];
    const float* W_hgate = (const float*)d_in[11];
    const float* b_hgate = (const float*)d_in[12];
    const float* W_vgate = (const float*)d_in[13];
    const float* b_vgate = (const float*)d_in[14];
    const float* Wo      = (const float*)d_in[15];
    float* out = (float*)d_out;

    float *qraw, *kraw, *vraw, *vgate, *outg;
    cudaGetSymbolAddress((void**)&qraw, g_qraw);
    cudaGetSymbolAddress((void**)&kraw, g_kraw);
    cudaGetSymbolAddress((void**)&vraw, g_vraw);
    cudaGetSymbolAddress((void**)&vgate, g_vgate);
    cudaGetSymbolAddress((void**)&outg, g_outg);

    dim3 gBig(DIMM / 128, ROWS / 128);  // (8, 32) = 256 blocks

    // 1) projections + gate logits
    tgemm_k<<<gBig, 256>>>(x, Wq, qraw, ROWS, DIMM, DIMM);
    tgemm_k<<<gBig, 256>>>(x, Wk, kraw, ROWS, DIMM, DIMM);
    tgemm_k<<<gBig, 256>>>(x, Wv, vraw, ROWS, DIMM, DIMM);
    tgemm_k<<<gBig, 256>>>(x, W_vgate, vgate, ROWS, DIMM, DIMM);
    hgate_k<<<ROWS / 8, 256>>>(x, W_hgate);

    // 2) norm/rope/scale -> pre-split tf32 hi/lo planes; memory kv slots
    normrope_k<<<(ROWS * NH) / 8, 256>>>(freqs, q_scale, k_scale);
    memprep_k<<<(NH * NMEM) / 8, 256>>>(mem_k, mem_v, k_scale);

    // 3) attention scores (pure LDS+MMA mainloop, causal tiles only)
    {
        int dsmem = 4 * 64 * DQP * (int)sizeof(float);  // 69,632 B
        cudaFuncSetAttribute(dots_k, cudaFuncAttributeMaxDynamicSharedMemorySize, dsmem);
        dots_k<<<dim3((JTOT + 63) / 64, SEQ / 64, BB * NH), 256, dsmem>>>();
    }

    // 4) talking-heads mix + causal softmax + post-mix (hi/lo plane output)
    {
        int smem = NH * JTOT * (int)sizeof(float);  // 66,560 B
        cudaFuncSetAttribute(mixsoft_k, cudaFuncAttributeMaxDynamicSharedMemorySize, smem);
        mixsoft_k<<<dim3(SEQ, BB), 256, smem>>>(W_pre, W_post);
    }

    // 5) attn @ v (pure LDS+MMA mainloop) + gates
    outgemm_k<<<dim3(SEQ / 64, BB * NH), 256>>>(b_hgate, b_vgate, outg);

    // 6) output projection
    tgemm_k<<<gBig, 256>>>(outg, Wo, out, ROWS, DIMM, DIMM);
}

// round 11
// speedup vs baseline: 1.0310x; 1.0310x over previous
#include <cuda_runtime.h>
#include <math.h>

#define BB 4
#define SEQ 1024
#define DIMM 1024
#define NH 16
#define DHD 64
#define NMEM 16
#define JTOT (SEQ + NMEM)   /* 1040 */
#define ROWS (BB * SEQ)     /* 4096 */
#define QKSCALE 10.0f

// ------------------------- device scratch (no allocs) -------------------------
__device__ float g_qraw[ROWS * DIMM];
__device__ float g_kraw[ROWS * DIMM];
__device__ float g_vraw[ROWS * DIMM];
__device__ float g_vgate[ROWS * DIMM];
__device__ float g_hgate[ROWS * NH];
__device__ float g_q[(size_t)BB * NH * SEQ * DHD];
__device__ float g_k[(size_t)BB * NH * JTOT * DHD];
__device__ float g_v[(size_t)BB * NH * JTOT * DHD];
__device__ float g_dots[(size_t)BB * NH * SEQ * JTOT];
__device__ float g_outg[ROWS * DIMM];

// ------------------------------ tf32 helpers ---------------------------------
__device__ __forceinline__ unsigned tf32b(float x) {
    unsigned u;
    asm("cvt.rna.tf32.f32 %0, %1;" : "=r"(u) : "f"(x));
    return u;
}
__device__ __forceinline__ void tf32pair(float x, unsigned& hi, unsigned& lo) {
    hi = tf32b(x);
    lo = tf32b(x - __uint_as_float(hi));
}
__device__ __forceinline__ void mma_tf32(float c[4], const unsigned a[4], const unsigned b[2]) {
    asm volatile(
        "mma.sync.aligned.m16n8k8.row.col.f32.tf32.tf32.f32 "
        "{%0,%1,%2,%3},{%4,%5,%6,%7},{%8,%9},{%0,%1,%2,%3};\n"
        : "+f"(c[0]), "+f"(c[1]), "+f"(c[2]), "+f"(c[3])
        : "r"(a[0]), "r"(a[1]), "r"(a[2]), "r"(a[3]), "r"(b[0]), "r"(b[1]));
}
__device__ __forceinline__ void cp16(void* smem, const void* gmem) {
    unsigned s = (unsigned)__cvta_generic_to_shared(smem);
    asm volatile("cp.async.cg.shared.global [%0], [%1], 16;\n" ::"r"(s), "l"(gmem));
}
#define CP_COMMIT asm volatile("cp.async.commit_group;\n")
#define CP_WAIT(n) asm volatile("cp.async.wait_group %0;\n" ::"n"(n))

__device__ __forceinline__ float sigm(float x) { return 1.f / (1.f + __expf(-x)); }

// ------ TF32 GEMM (trunk): C = A @ B, cp.async 2-stage, cvt in loop ----------
#define APITCH 20
#define BPITCH 136
__global__ __launch_bounds__(256, 2) void tgemm_k(const float* __restrict__ A,
                                                  const float* __restrict__ Bm,
                                                  float* __restrict__ C,
                                                  int Mn, int Nn, int Kn) {
    __shared__ float As[2][128 * APITCH];
    __shared__ float Bs[2][16 * BPITCH];
    int tid = threadIdx.x;
    int row0 = blockIdx.y * 128, col0 = blockIdx.x * 128;
    int w = tid >> 5, lane = tid & 31;
    int wm = (w & 1) * 64, wn = (w >> 1) * 32;
    int qr = lane >> 2, qc = lane & 3;

    float acc[4][4][4];
#pragma unroll
    for (int i = 0; i < 4; i++)
#pragma unroll
        for (int j = 0; j < 4; j++)
#pragma unroll
            for (int u = 0; u < 4; u++) acc[i][j][u] = 0.f;

    int KT = Kn >> 4;
    {
#pragma unroll
        for (int it = 0; it < 2; it++) {
            int c = tid + it * 256;
            int ar = c >> 2, ac = (c & 3) * 4;
            cp16(&As[0][ar * APITCH + ac], &A[(size_t)(row0 + ar) * Kn + ac]);
            int br = c >> 5, bc = (c & 31) * 4;
            cp16(&Bs[0][br * BPITCH + bc], &Bm[(size_t)br * Nn + col0 + bc]);
        }
        CP_COMMIT;
    }
    for (int kt = 0; kt < KT; kt++) {
        if (kt + 1 < KT) {
            int k0 = (kt + 1) << 4;
            int st = (kt + 1) & 1;
#pragma unroll
            for (int it = 0; it < 2; it++) {
                int c = tid + it * 256;
                int ar = c >> 2, ac = (c & 3) * 4;
                cp16(&As[st][ar * APITCH + ac], &A[(size_t)(row0 + ar) * Kn + k0 + ac]);
                int br = c >> 5, bc = (c & 31) * 4;
                cp16(&Bs[st][br * BPITCH + bc], &Bm[(size_t)(k0 + br) * Nn + col0 + bc]);
            }
            CP_COMMIT;
            CP_WAIT(1);
        } else {
            CP_WAIT(0);
        }
        __syncthreads();
        const float* as = As[kt & 1];
        const float* bs = Bs[kt & 1];
#pragma unroll
        for (int ks = 0; ks < 2; ks++) {
            int k = ks * 8 + qc;
            unsigned af[4][4], bf[4][2];
#pragma unroll
            for (int mi = 0; mi < 4; mi++) {
                int m = wm + mi * 16 + qr;
                af[mi][0] = tf32b(as[m * APITCH + k]);
                af[mi][1] = tf32b(as[(m + 8) * APITCH + k]);
                af[mi][2] = tf32b(as[m * APITCH + k + 4]);
                af[mi][3] = tf32b(as[(m + 8) * APITCH + k + 4]);
            }
#pragma unroll
            for (int ni = 0; ni < 4; ni++) {
                int n = wn + ni * 8 + qr;
                bf[ni][0] = tf32b(bs[k * BPITCH + n]);
                bf[ni][1] = tf32b(bs[(k + 4) * BPITCH + n]);
            }
#pragma unroll
            for (int mi = 0; mi < 4; mi++)
#pragma unroll
                for (int ni = 0; ni < 4; ni++) mma_tf32(acc[mi][ni], af[mi], bf[ni]);
        }
        __syncthreads();
    }
#pragma unroll
    for (int mi = 0; mi < 4; mi++) {
        int r = row0 + wm + mi * 16 + qr;
#pragma unroll
        for (int ni = 0; ni < 4; ni++) {
            int c = col0 + wn + ni * 8 + 2 * qc;
            *reinterpret_cast<float2*>(&C[(size_t)r * Nn + c]) =
                make_float2(acc[mi][ni][0], acc[mi][ni][1]);
            *reinterpret_cast<float2*>(&C[(size_t)(r + 8) * Nn + c]) =
                make_float2(acc[mi][ni][2], acc[mi][ni][3]);
        }
    }
}

// ----------------- head gate logits: warp per row, 16 accums ------------------
__global__ __launch_bounds__(256) void hgate_k(const float* __restrict__ x,
                                               const float* __restrict__ W) {
    int r = (blockIdx.x * blockDim.x + threadIdx.x) >> 5;
    int lane = threadIdx.x & 31;
    const float* xr = x + (size_t)r * DIMM;
    float a[16];
#pragma unroll
    for (int h = 0; h < 16; h++) a[h] = 0.f;
    for (int d = lane; d < DIMM; d += 32) {
        float xv = xr[d];
        const float4* wr = reinterpret_cast<const float4*>(W + d * NH);
        float4 w0 = wr[0], w1 = wr[1], w2 = wr[2], w3 = wr[3];
        a[0] += xv * w0.x; a[1] += xv * w0.y; a[2] += xv * w0.z; a[3] += xv * w0.w;
        a[4] += xv * w1.x; a[5] += xv * w1.y; a[6] += xv * w1.z; a[7] += xv * w1.w;
        a[8] += xv * w2.x; a[9] += xv * w2.y; a[10] += xv * w2.z; a[11] += xv * w2.w;
        a[12] += xv * w3.x; a[13] += xv * w3.y; a[14] += xv * w3.z; a[15] += xv * w3.w;
    }
#pragma unroll
    for (int h = 0; h < 16; h++)
#pragma unroll
        for (int o = 16; o; o >>= 1) a[h] += __shfl_xor_sync(0xffffffffu, a[h], o);
    if (lane == 0) {
        float4* dst = reinterpret_cast<float4*>(&g_hgate[r * NH]);
        dst[0] = make_float4(a[0], a[1], a[2], a[3]);
        dst[1] = make_float4(a[4], a[5], a[6], a[7]);
        dst[2] = make_float4(a[8], a[9], a[10], a[11]);
        dst[3] = make_float4(a[12], a[13], a[14], a[15]);
    }
}

// ------------- l2norm + per-dim scale + RoPE for q,k; transpose v -------------
__global__ __launch_bounds__(256) void normrope_k(const float* __restrict__ freqs,
                                                  const float* __restrict__ q_scale,
                                                  const float* __restrict__ k_scale) {
    int gw = (blockIdx.x * blockDim.x + threadIdx.x) >> 5;
    int lane = threadIdx.x & 31;
    int row = gw / NH, h = gw - row * NH;
    int b = row / SEQ, n = row - b * SEQ;
    int d0 = lane * 2;
    size_t src = (size_t)row * DIMM + h * DHD + d0;
    float f = freqs[n * DHD + d0];
    float sf, cf;
    sincosf(f, &sf, &cf);
    {   // q
        float x0 = g_qraw[src], x1 = g_qraw[src + 1];
        float ss = x0 * x0 + x1 * x1;
#pragma unroll
        for (int o = 16; o; o >>= 1) ss += __shfl_xor_sync(0xffffffffu, ss, o);
        float inv = 1.f / fmaxf(sqrtf(ss), 1e-12f);
        x0 = x0 * inv * q_scale[h * DHD + d0];
        x1 = x1 * inv * q_scale[h * DHD + d0 + 1];
        size_t dst = ((size_t)(b * NH + h) * SEQ + n) * DHD + d0;
        g_q[dst] = x0 * cf - x1 * sf;
        g_q[dst + 1] = x1 * cf + x0 * sf;
    }
    {   // k
        float x0 = g_kraw[src], x1 = g_kraw[src + 1];
        float ss = x0 * x0 + x1 * x1;
#pragma unroll
        for (int o = 16; o; o >>= 1) ss += __shfl_xor_sync(0xffffffffu, ss, o);
        float inv = 1.f / fmaxf(sqrtf(ss), 1e-12f);
        x0 = x0 * inv * k_scale[h * DHD + d0];
        x1 = x1 * inv * k_scale[h * DHD + d0 + 1];
        size_t dst = ((size_t)(b * NH + h) * JTOT + NMEM + n) * DHD + d0;
        g_k[dst] = x0 * cf - x1 * sf;
        g_k[dst + 1] = x1 * cf + x0 * sf;
    }
    {   // v
        size_t dst = ((size_t)(b * NH + h) * JTOT + NMEM + n) * DHD + d0;
        g_v[dst] = g_vraw[src];
        g_v[dst + 1] = g_vraw[src + 1];
    }
}

// ------------- memory kv slots: l2norm(mem_k)*k_scale, copy mem_v -------------
__global__ __launch_bounds__(256) void memprep_k(const float* __restrict__ mem_k,
                                                 const float* __restrict__ mem_v,
                                                 const float* __restrict__ k_scale) {
    int gw = (blockIdx.x * blockDim.x + threadIdx.x) >> 5;
    int lane = threadIdx.x & 31;
    int h = gw / NMEM, m = gw - h * NMEM;
    int d0 = lane * 2;
    float x0 = mem_k[(h * NMEM + m) * DHD + d0];
    float x1 = mem_k[(h * NMEM + m) * DHD + d0 + 1];
    float ss = x0 * x0 + x1 * x1;
#pragma unroll
    for (int o = 16; o; o >>= 1) ss += __shfl_xor_sync(0xffffffffu, ss, o);
    float inv = 1.f / fmaxf(sqrtf(ss), 1e-12f);
    x0 = x0 * inv * k_scale[h * DHD + d0];
    x1 = x1 * inv * k_scale[h * DHD + d0 + 1];
    float v0 = mem_v[(h * NMEM + m) * DHD + d0];
    float v1 = mem_v[(h * NMEM + m) * DHD + d0 + 1];
    for (int b = 0; b < BB; b++) {
        size_t dst = ((size_t)(b * NH + h) * JTOT + m) * DHD + d0;
        g_k[dst] = x0;
        g_k[dst + 1] = x1;
        g_v[dst] = v0;
        g_v[dst + 1] = v1;
    }
}

// --- dots = QKSCALE * q.k: 3xTF32 mma, hi/lo planes precomputed in smem -------
#define DQP 68
__global__ __launch_bounds__(256) void dots_k() {
    int i0 = blockIdx.y * 64;
    int j0 = blockIdx.x * 64;
    if (j0 > i0 + 63 + NMEM) return;
    extern __shared__ float dsm[];
    float* Qh = dsm;
    float* Ql = Qh + 64 * DQP;
    float* Kh = Ql + 64 * DQP;
    float* Kl = Kh + 64 * DQP;
    int bh = blockIdx.z;
    const float* Q = g_q + (size_t)bh * SEQ * DHD;
    const float* K = g_k + (size_t)bh * JTOT * DHD;
    int tid = threadIdx.x;
#pragma unroll
    for (int it = 0; it < 4; it++) {
        int c = tid + it * 256;
        int r = c >> 4, d4 = (c & 15) * 4;
        float4 qv = *reinterpret_cast<const float4*>(&Q[(size_t)(i0 + r) * DHD + d4]);
        unsigned h0, l0, h1, l1, h2, l2, h3, l3;
        tf32pair(qv.x, h0, l0); tf32pair(qv.y, h1, l1);
        tf32pair(qv.z, h2, l2); tf32pair(qv.w, h3, l3);
        *reinterpret_cast<uint4*>(&Qh[r * DQP + d4]) = make_uint4(h0, h1, h2, h3);
        *reinterpret_cast<uint4*>(&Ql[r * DQP + d4]) = make_uint4(l0, l1, l2, l3);
        int jj = j0 + r;
        float4 kv = make_float4(0.f, 0.f, 0.f, 0.f);
        if (jj < JTOT) kv = *reinterpret_cast<const float4*>(&K[(size_t)jj * DHD + d4]);
        tf32pair(kv.x, h0, l0); tf32pair(kv.y, h1, l1);
        tf32pair(kv.z, h2, l2); tf32pair(kv.w, h3, l3);
        *reinterpret_cast<uint4*>(&Kh[r * DQP + d4]) = make_uint4(h0, h1, h2, h3);
        *reinterpret_cast<uint4*>(&Kl[r * DQP + d4]) = make_uint4(l0, l1, l2, l3);
    }
    __syncthreads();
    int w = tid >> 5, lane = tid & 31;
    int wm = (w >> 1) * 16, wn = (w & 1) * 32;
    int qr = lane >> 2, qc = lane & 3;
    float acc[4][4] = {};
#pragma unroll
    for (int kk = 0; kk < 8; kk++) {
        int k = kk * 8 + qc;
        unsigned ah[4], al[4];
        ah[0] = __float_as_uint(Qh[(wm + qr) * DQP + k]);
        ah[1] = __float_as_uint(Qh[(wm + qr + 8) * DQP + k]);
        ah[2] = __float_as_uint(Qh[(wm + qr) * DQP + k + 4]);
        ah[3] = __float_as_uint(Qh[(wm + qr + 8) * DQP + k + 4]);
        al[0] = __float_as_uint(Ql[(wm + qr) * DQP + k]);
        al[1] = __float_as_uint(Ql[(wm + qr + 8) * DQP + k]);
        al[2] = __float_as_uint(Ql[(wm + qr) * DQP + k + 4]);
        al[3] = __float_as_uint(Ql[(wm + qr + 8) * DQP + k + 4]);
#pragma unroll
        for (int ni = 0; ni < 4; ni++) {
            int n = wn + ni * 8 + qr;
            unsigned bh2[2], bl2[2];
            bh2[0] = __float_as_uint(Kh[n * DQP + k]);
            bh2[1] = __float_as_uint(Kh[n * DQP + k + 4]);
            bl2[0] = __float_as_uint(Kl[n * DQP + k]);
            bl2[1] = __float_as_uint(Kl[n * DQP + k + 4]);
            mma_tf32(acc[ni], ah, bh2);
            mma_tf32(acc[ni], ah, bl2);
            mma_tf32(acc[ni], al, bh2);
        }
    }
    float* D = g_dots + (size_t)bh * SEQ * JTOT;
#pragma unroll
    for (int ni = 0; ni < 4; ni++) {
        int i = i0 + wm + qr;
        int j = j0 + wn + ni * 8 + 2 * qc;
        if (j < JTOT) {
            *reinterpret_cast<float2*>(&D[(size_t)i * JTOT + j]) =
                make_float2(acc[ni][0] * QKSCALE, acc[ni][1] * QKSCALE);
            *reinterpret_cast<float2*>(&D[(size_t)(i + 8) * JTOT + j]) =
                make_float2(acc[ni][2] * QKSCALE, acc[ni][3] * QKSCALE);
        }
    }
}

// ------ pre-mix + causal softmax + post-mix, largest-first, band zeros --------
__global__ __launch_bounds__(256) void mixsoft_k(const float* __restrict__ W_pre,
                                                 const float* __restrict__ W_post) {
    extern __shared__ float S[];  // NH * JTOT
    __shared__ float wpre[NH * NH], wpost[NH * NH], inv_l[NH];
    int i = SEQ - 1 - (int)blockIdx.x;  // largest jcnt scheduled first
    int b = blockIdx.y;
    int tid = threadIdx.x;
    wpre[tid] = W_pre[tid];
    wpost[tid] = W_post[tid];
    int jcnt = i + NMEM + 1;
    size_t base = ((size_t)(b * NH) * SEQ + i) * JTOT;
    for (int h = 0; h < NH; h++) {
        size_t off = base + (size_t)h * SEQ * JTOT;
        for (int j = tid; j < jcnt; j += 256) S[h * JTOT + j] = g_dots[off + j];
    }
    __syncthreads();
    for (int j = tid; j < jcnt; j += 256) {
        float sv[NH];
#pragma unroll
        for (int h = 0; h < NH; h++) sv[h] = S[h * JTOT + j];
#pragma unroll
        for (int g = 0; g < NH; g++) {
            float a = 0.f;
#pragma unroll
            for (int h = 0; h < NH; h++) a += wpre[g * NH + h] * sv[h];
            S[g * JTOT + j] = a;
        }
    }
    __syncthreads();
    int w = tid >> 5, lane = tid & 31;
    for (int g = w; g < NH; g += 8) {
        float mx = -3.0e38f;
        for (int j = lane; j < jcnt; j += 32) mx = fmaxf(mx, S[g * JTOT + j]);
#pragma unroll
        for (int o = 16; o; o >>= 1) mx = fmaxf(mx, __shfl_xor_sync(0xffffffffu, mx, o));
        float sum = 0.f;
        for (int j = lane; j < jcnt; j += 32) {
            float e = __expf(S[g * JTOT + j] - mx);
            S[g * JTOT + j] = e;
            sum += e;
        }
#pragma unroll
        for (int o = 16; o; o >>= 1) sum += __shfl_xor_sync(0xffffffffu, sum, o);
        if (lane == 0) inv_l[g] = 1.f / sum;
    }
    __syncthreads();
    for (int j = tid; j < jcnt; j += 256) {
        float pv[NH];
#pragma unroll
        for (int h = 0; h < NH; h++) pv[h] = S[h * JTOT + j] * inv_l[h];
#pragma unroll
        for (int g = 0; g < NH; g++) {
            float a = 0.f;
#pragma unroll
            for (int h = 0; h < NH; h++) a += wpost[g * NH + h] * pv[h];
            g_dots[base + (size_t)g * SEQ * JTOT + j] = a;
        }
    }
    // zero only the band outgemm will read: [jcnt, (i&~63)+80)
    int zend = (i & ~63) + 80;
    if (zend > JTOT) zend = JTOT;
    for (int j = jcnt + tid; j < zend; j += 256) {
#pragma unroll
        for (int g = 0; g < NH; g++) g_dots[base + (size_t)g * SEQ * JTOT + j] = 0.f;
    }
}

// -- out = attn @ v: 2-stage cp.async pipeline, fill-convert hi/lo, + gates ----
#define OPITCH 20
#define VPITCH 17
__global__ __launch_bounds__(256) void outgemm_k(const float* __restrict__ b_h,
                                                 const float* __restrict__ b_v,
                                                 float* __restrict__ outg) {
    __shared__ float Araw[2][64 * OPITCH];  // raw attn staging (cp.async)
    __shared__ float Ah[64 * OPITCH];       // converted hi/lo planes
    __shared__ float Al[64 * OPITCH];
    __shared__ float Vh[64 * VPITCH];       // V^T [d][k] hi/lo
    __shared__ float Vl[64 * VPITCH];
    int bg = blockIdx.y;
    int b = bg >> 4, g = bg & 15;
    int i0 = blockIdx.x * 64;
    const float* Arow = g_dots + (size_t)bg * SEQ * JTOT;
    const float* V = g_v + (size_t)bg * JTOT * DHD;
    int tid = threadIdx.x;
    int w = tid >> 5, lane = tid & 31;
    int wm = (w >> 1) * 16, wn = (w & 1) * 32;
    int qr = lane >> 2, qc = lane & 3;
    int ar = tid >> 2, ac4 = (tid & 3) * 4;   // A fill: row, col*4
    int vk = tid >> 4, vd4 = (tid & 15) * 4;  // V fill: k-row, d*4
    float acc[4][4] = {};
    int kmax = i0 + 80;
    if (kmax > JTOT) kmax = JTOT;
    int KT = kmax >> 4;

    // preload stage 0: A via cp.async, V via register
    cp16(&Araw[0][ar * OPITCH + ac4], &Arow[(size_t)(i0 + ar) * JTOT + ac4]);
    CP_COMMIT;
    float4 vreg = *reinterpret_cast<const float4*>(&V[(size_t)vk * DHD + vd4]);

    for (int kt = 0; kt < KT; kt++) {
        int st = kt & 1;
        int k0n = (kt + 1) << 4;
        if (kt + 1 < KT) {
            cp16(&Araw[st ^ 1][ar * OPITCH + ac4],
                 &Arow[(size_t)(i0 + ar) * JTOT + k0n + ac4]);
            CP_COMMIT;
            CP_WAIT(1);
        } else {
            CP_WAIT(0);
        }
        __syncthreads();  // Araw[st] visible; prior compute done with Ah/Al/Vh/Vl
        // fill-convert A and V into hi/lo planes
        {
            float4 av = *reinterpret_cast<const float4*>(&Araw[st][ar * OPITCH + ac4]);
            unsigned h0, l0, h1, l1, h2, l2, h3, l3;
            tf32pair(av.x, h0, l0); tf32pair(av.y, h1, l1);
            tf32pair(av.z, h2, l2); tf32pair(av.w, h3, l3);
            *reinterpret_cast<uint4*>(&Ah[ar * OPITCH + ac4]) = make_uint4(h0, h1, h2, h3);
            *reinterpret_cast<uint4*>(&Al[ar * OPITCH + ac4]) = make_uint4(l0, l1, l2, l3);
            unsigned vh0, vl0, vh1, vl1, vh2, vl2, vh3, vl3;
            tf32pair(vreg.x, vh0, vl0); tf32pair(vreg.y, vh1, vl1);
            tf32pair(vreg.z, vh2, vl2); tf32pair(vreg.w, vh3, vl3);
            Vh[(vd4 + 0) * VPITCH + vk] = __uint_as_float(vh0);
            Vh[(vd4 + 1) * VPITCH + vk] = __uint_as_float(vh1);
            Vh[(vd4 + 2) * VPITCH + vk] = __uint_as_float(vh2);
            Vh[(vd4 + 3) * VPITCH + vk] = __uint_as_float(vh3);
            Vl[(vd4 + 0) * VPITCH + vk] = __uint_as_float(vl0);
            Vl[(vd4 + 1) * VPITCH + vk] = __uint_as_float(vl1);
            Vl[(vd4 + 2) * VPITCH + vk] = __uint_as_float(vl2);
            Vl[(vd4 + 3) * VPITCH + vk] = __uint_as_float(vl3);
        }
        // prefetch next V tile into registers (overlaps with compute below)
        float4 vnext = vreg;
        if (kt + 1 < KT)
            vnext = *reinterpret_cast<const float4*>(&V[(size_t)(k0n + vk) * DHD + vd4]);
        __syncthreads();
#pragma unroll
        for (int ks = 0; ks < 2; ks++) {
            int k = ks * 8 + qc;
            unsigned ah[4], al[4];
            ah[0] = __float_as_uint(Ah[(wm + qr) * OPITCH + k]);
            ah[1] = __float_as_uint(Ah[(wm + qr + 8) * OPITCH + k]);
            ah[2] = __float_as_uint(Ah[(wm + qr) * OPITCH + k + 4]);
            ah[3] = __float_as_uint(Ah[(wm + qr + 8) * OPITCH + k + 4]);
            al[0] = __float_as_uint(Al[(wm + qr) * OPITCH + k]);
            al[1] = __float_as_uint(Al[(wm + qr + 8) * OPITCH + k]);
            al[2] = __float_as_uint(Al[(wm + qr) * OPITCH + k + 4]);
            al[3] = __float_as_uint(Al[(wm + qr + 8) * OPITCH + k + 4]);
#pragma unroll
            for (int ni = 0; ni < 4; ni++) {
                int n = wn + ni * 8 + qr;
                unsigned bh2[2], bl2[2];
                bh2[0] = __float_as_uint(Vh[n * VPITCH + k]);
                bh2[1] = __float_as_uint(Vh[n * VPITCH + k + 4]);
                bl2[0] = __float_as_uint(Vl[n * VPITCH + k]);
                bl2[1] = __float_as_uint(Vl[n * VPITCH + k + 4]);
                mma_tf32(acc[ni], ah, bh2);
                mma_tf32(acc[ni], ah, bl2);
                mma_tf32(acc[ni], al, bh2);
            }
        }
        vreg = vnext;
    }
    __syncthreads();
#pragma unroll
    for (int rr = 0; rr < 2; rr++) {
        int i = i0 + wm + qr + rr * 8;
        int r = b * SEQ + i;
        float hg = sigm(g_hgate[r * NH + g] + b_h[g]);
#pragma unroll
        for (int ni = 0; ni < 4; ni++) {
            int c = g * DHD + wn + ni * 8 + 2 * qc;
            float2 vgl = *reinterpret_cast<const float2*>(&g_vgate[(size_t)r * DIMM + c]);
            float2 bvl = *reinterpret_cast<const float2*>(&b_v[c]);
            float o0 = acc[ni][rr * 2 + 0] * hg * sigm(vgl.x + bvl.x);
            float o1 = acc[ni][rr * 2 + 1] * hg * sigm(vgl.y + bvl.y);
            *reinterpret_cast<float2*>(&outg[(size_t)r * DIMM + c]) = make_float2(o0, o1);
        }
    }
}

// ------------------------------------------------------------------------------
extern "C" void kernel_launch(void* const* d_in, const int* in_sizes, int n_in,
                              void* d_out, int out_size) {
    const float* x       = (const float*)d_in[0];
    const float* freqs   = (const float*)d_in[1];
    const float* Wq      = (const float*)d_in[2];
    const float* Wk      = (const float*)d_in[3];
    const float* Wv      = (const float*)d_in[4];
    const float* q_scale = (const float*)d_in[5];
    const float* k_scale = (const float*)d_in[6];
    const float* mem_k   = (const float*)d_in[7];
    const float* mem_v   = (const float*)d_in[8];
    const float* W_pre   = (const float*)d_in[9];
    const float* W_post  = (const float*)d_in[10];
    const float* W_hgate = (const float*)d_in[11];
    const float* b_hgate = (const float*)d_in[12];
    const float* W_vgate = (const float*)d_in[13];
    const float* b_vgate = (const float*)d_in[14];
    const float* Wo      = (const float*)d_in[15];
    float* out = (float*)d_out;

    float *qraw, *kraw, *vraw, *vgate, *outg;
    cudaGetSymbolAddress((void**)&qraw, g_qraw);
    cudaGetSymbolAddress((void**)&kraw, g_kraw);
    cudaGetSymbolAddress((void**)&vraw, g_vraw);
    cudaGetSymbolAddress((void**)&vgate, g_vgate);
    cudaGetSymbolAddress((void**)&outg, g_outg);

    dim3 gBig(DIMM / 128, ROWS / 128);  // (8, 32) = 256 blocks

    // 1) projections + gate logits
    tgemm_k<<<gBig, 256>>>(x, Wq, qraw, ROWS, DIMM, DIMM);
    tgemm_k<<<gBig, 256>>>(x, Wk, kraw, ROWS, DIMM, DIMM);
    tgemm_k<<<gBig, 256>>>(x, Wv, vraw, ROWS, DIMM, DIMM);
    tgemm_k<<<gBig, 256>>>(x, W_vgate, vgate, ROWS, DIMM, DIMM);
    hgate_k<<<ROWS / 8, 256>>>(x, W_hgate);

    // 2) l2norm + scale + rope + head-major layout; memory kv slots
    normrope_k<<<(ROWS * NH) / 8, 256>>>(freqs, q_scale, k_scale);
    memprep_k<<<(NH * NMEM) / 8, 256>>>(mem_k, mem_v, k_scale);

    // 3) attention scores (3xTF32 mma, hi/lo pre-split in smem, causal tiles)
    {
        int dsmem = 4 * 64 * DQP * (int)sizeof(float);  // 69,632 B
        cudaFuncSetAttribute(dots_k, cudaFuncAttributeMaxDynamicSharedMemorySize, dsmem);
        dots_k<<<dim3((JTOT + 63) / 64, SEQ / 64, BB * NH), 256, dsmem>>>();
    }

    // 4) talking-heads mix + causal softmax + post-mix
    {
        int smem = NH * JTOT * (int)sizeof(float);  // 66,560 B
        cudaFuncSetAttribute(mixsoft_k, cudaFuncAttributeMaxDynamicSharedMemorySize, smem);
        mixsoft_k<<<dim3(SEQ, BB), 256, smem>>>(W_pre, W_post);
    }

    // 5) attn @ v (pipelined, 3xTF32 mma) + gates
    outgemm_k<<<dim3(SEQ / 64, BB * NH), 256>>>(b_hgate, b_vgate, outg);

    // 6) output projection
    tgemm_k<<<gBig, 256>>>(outg, Wo, out, ROWS, DIMM, DIMM);
}

// round 12
// speedup vs baseline: 1.0825x; 1.0500x over previous
#include <cuda_runtime.h>
#include <math.h>

#define BB 4
#define SEQ 1024
#define DIMM 1024
#define NH 16
#define DHD 64
#define NMEM 16
#define JTOT (SEQ + NMEM)   /* 1040 */
#define ROWS (BB * SEQ)     /* 4096 */
#define QKSCALE 10.0f

// ------------------------- device scratch (no allocs) -------------------------
__device__ float g_qraw[ROWS * DIMM];
__device__ float g_kraw[ROWS * DIMM];
__device__ float g_vraw[ROWS * DIMM];
__device__ float g_vgate[ROWS * DIMM];
__device__ float g_hgate[ROWS * NH];
__device__ float g_q[(size_t)BB * NH * SEQ * DHD];
__device__ float g_k[(size_t)BB * NH * JTOT * DHD];
__device__ float g_v[(size_t)BB * NH * JTOT * DHD];
__device__ float g_dots[(size_t)BB * NH * SEQ * JTOT];
__device__ float g_outg[ROWS * DIMM];

// ------------------------------ tf32 helpers ---------------------------------
__device__ __forceinline__ unsigned tf32b(float x) {
    unsigned u;
    asm("cvt.rna.tf32.f32 %0, %1;" : "=r"(u) : "f"(x));
    return u;
}
__device__ __forceinline__ void tf32pair(float x, unsigned& hi, unsigned& lo) {
    hi = tf32b(x);
    lo = tf32b(x - __uint_as_float(hi));
}
__device__ __forceinline__ void mma_tf32(float c[4], const unsigned a[4], const unsigned b[2]) {
    asm volatile(
        "mma.sync.aligned.m16n8k8.row.col.f32.tf32.tf32.f32 "
        "{%0,%1,%2,%3},{%4,%5,%6,%7},{%8,%9},{%0,%1,%2,%3};\n"
        : "+f"(c[0]), "+f"(c[1]), "+f"(c[2]), "+f"(c[3])
        : "r"(a[0]), "r"(a[1]), "r"(a[2]), "r"(a[3]), "r"(b[0]), "r"(b[1]));
}
__device__ __forceinline__ void cp16(void* smem, const void* gmem) {
    unsigned s = (unsigned)__cvta_generic_to_shared(smem);
    asm volatile("cp.async.cg.shared.global [%0], [%1], 16;\n" ::"r"(s), "l"(gmem));
}
#define CP_COMMIT asm volatile("cp.async.commit_group;\n")
#define CP_WAIT(n) asm volatile("cp.async.wait_group %0;\n" ::"n"(n))

__device__ __forceinline__ float sigm(float x) { return 1.f / (1.f + __expf(-x)); }

// ------ TF32 GEMM (trunk): C = A @ B, cp.async 2-stage, cvt in loop ----------
#define APITCH 20
#define BPITCH 136
__global__ __launch_bounds__(256, 2) void tgemm_k(const float* __restrict__ A,
                                                  const float* __restrict__ Bm,
                                                  float* __restrict__ C,
                                                  int Mn, int Nn, int Kn) {
    __shared__ float As[2][128 * APITCH];
    __shared__ float Bs[2][16 * BPITCH];
    int tid = threadIdx.x;
    int row0 = blockIdx.y * 128, col0 = blockIdx.x * 128;
    int w = tid >> 5, lane = tid & 31;
    int wm = (w & 1) * 64, wn = (w >> 1) * 32;
    int qr = lane >> 2, qc = lane & 3;

    float acc[4][4][4];
#pragma unroll
    for (int i = 0; i < 4; i++)
#pragma unroll
        for (int j = 0; j < 4; j++)
#pragma unroll
            for (int u = 0; u < 4; u++) acc[i][j][u] = 0.f;

    int KT = Kn >> 4;
    {
#pragma unroll
        for (int it = 0; it < 2; it++) {
            int c = tid + it * 256;
            int ar = c >> 2, ac = (c & 3) * 4;
            cp16(&As[0][ar * APITCH + ac], &A[(size_t)(row0 + ar) * Kn + ac]);
            int br = c >> 5, bc = (c & 31) * 4;
            cp16(&Bs[0][br * BPITCH + bc], &Bm[(size_t)br * Nn + col0 + bc]);
        }
        CP_COMMIT;
    }
    for (int kt = 0; kt < KT; kt++) {
        if (kt + 1 < KT) {
            int k0 = (kt + 1) << 4;
            int st = (kt + 1) & 1;
#pragma unroll
            for (int it = 0; it < 2; it++) {
                int c = tid + it * 256;
                int ar = c >> 2, ac = (c & 3) * 4;
                cp16(&As[st][ar * APITCH + ac], &A[(size_t)(row0 + ar) * Kn + k0 + ac]);
                int br = c >> 5, bc = (c & 31) * 4;
                cp16(&Bs[st][br * BPITCH + bc], &Bm[(size_t)(k0 + br) * Nn + col0 + bc]);
            }
            CP_COMMIT;
            CP_WAIT(1);
        } else {
            CP_WAIT(0);
        }
        __syncthreads();
        const float* as = As[kt & 1];
        const float* bs = Bs[kt & 1];
#pragma unroll
        for (int ks = 0; ks < 2; ks++) {
            int k = ks * 8 + qc;
            unsigned af[4][4], bf[4][2];
#pragma unroll
            for (int mi = 0; mi < 4; mi++) {
                int m = wm + mi * 16 + qr;
                af[mi][0] = tf32b(as[m * APITCH + k]);
                af[mi][1] = tf32b(as[(m + 8) * APITCH + k]);
                af[mi][2] = tf32b(as[m * APITCH + k + 4]);
                af[mi][3] = tf32b(as[(m + 8) * APITCH + k + 4]);
            }
#pragma unroll
            for (int ni = 0; ni < 4; ni++) {
                int n = wn + ni * 8 + qr;
                bf[ni][0] = tf32b(bs[k * BPITCH + n]);
                bf[ni][1] = tf32b(bs[(k + 4) * BPITCH + n]);
            }
#pragma unroll
            for (int mi = 0; mi < 4; mi++)
#pragma unroll
                for (int ni = 0; ni < 4; ni++) mma_tf32(acc[mi][ni], af[mi], bf[ni]);
        }
        __syncthreads();
    }
#pragma unroll
    for (int mi = 0; mi < 4; mi++) {
        int r = row0 + wm + mi * 16 + qr;
#pragma unroll
        for (int ni = 0; ni < 4; ni++) {
            int c = col0 + wn + ni * 8 + 2 * qc;
            *reinterpret_cast<float2*>(&C[(size_t)r * Nn + c]) =
                make_float2(acc[mi][ni][0], acc[mi][ni][1]);
            *reinterpret_cast<float2*>(&C[(size_t)(r + 8) * Nn + c]) =
                make_float2(acc[mi][ni][2], acc[mi][ni][3]);
        }
    }
}

// ----------------- head gate logits: warp per row, 16 accums ------------------
__global__ __launch_bounds__(256) void hgate_k(const float* __restrict__ x,
                                               const float* __restrict__ W) {
    int r = (blockIdx.x * blockDim.x + threadIdx.x) >> 5;
    int lane = threadIdx.x & 31;
    const float* xr = x + (size_t)r * DIMM;
    float a[16];
#pragma unroll
    for (int h = 0; h < 16; h++) a[h] = 0.f;
    for (int d = lane; d < DIMM; d += 32) {
        float xv = xr[d];
        const float4* wr = reinterpret_cast<const float4*>(W + d * NH);
        float4 w0 = wr[0], w1 = wr[1], w2 = wr[2], w3 = wr[3];
        a[0] += xv * w0.x; a[1] += xv * w0.y; a[2] += xv * w0.z; a[3] += xv * w0.w;
        a[4] += xv * w1.x; a[5] += xv * w1.y; a[6] += xv * w1.z; a[7] += xv * w1.w;
        a[8] += xv * w2.x; a[9] += xv * w2.y; a[10] += xv * w2.z; a[11] += xv * w2.w;
        a[12] += xv * w3.x; a[13] += xv * w3.y; a[14] += xv * w3.z; a[15] += xv * w3.w;
    }
#pragma unroll
    for (int h = 0; h < 16; h++)
#pragma unroll
        for (int o = 16; o; o >>= 1) a[h] += __shfl_xor_sync(0xffffffffu, a[h], o);
    if (lane == 0) {
        float4* dst = reinterpret_cast<float4*>(&g_hgate[r * NH]);
        dst[0] = make_float4(a[0], a[1], a[2], a[3]);
        dst[1] = make_float4(a[4], a[5], a[6], a[7]);
        dst[2] = make_float4(a[8], a[9], a[10], a[11]);
        dst[3] = make_float4(a[12], a[13], a[14], a[15]);
    }
}

// ------------- l2norm + per-dim scale + RoPE for q,k; transpose v -------------
__global__ __launch_bounds__(256) void normrope_k(const float* __restrict__ freqs,
                                                  const float* __restrict__ q_scale,
                                                  const float* __restrict__ k_scale) {
    int gw = (blockIdx.x * blockDim.x + threadIdx.x) >> 5;
    int lane = threadIdx.x & 31;
    int row = gw / NH, h = gw - row * NH;
    int b = row / SEQ, n = row - b * SEQ;
    int d0 = lane * 2;
    size_t src = (size_t)row * DIMM + h * DHD + d0;
    float f = freqs[n * DHD + d0];
    float sf, cf;
    sincosf(f, &sf, &cf);
    {   // q
        float x0 = g_qraw[src], x1 = g_qraw[src + 1];
        float ss = x0 * x0 + x1 * x1;
#pragma unroll
        for (int o = 16; o; o >>= 1) ss += __shfl_xor_sync(0xffffffffu, ss, o);
        float inv = 1.f / fmaxf(sqrtf(ss), 1e-12f);
        x0 = x0 * inv * q_scale[h * DHD + d0];
        x1 = x1 * inv * q_scale[h * DHD + d0 + 1];
        size_t dst = ((size_t)(b * NH + h) * SEQ + n) * DHD + d0;
        g_q[dst] = x0 * cf - x1 * sf;
        g_q[dst + 1] = x1 * cf + x0 * sf;
    }
    {   // k
        float x0 = g_kraw[src], x1 = g_kraw[src + 1];
        float ss = x0 * x0 + x1 * x1;
#pragma unroll
        for (int o = 16; o; o >>= 1) ss += __shfl_xor_sync(0xffffffffu, ss, o);
        float inv = 1.f / fmaxf(sqrtf(ss), 1e-12f);
        x0 = x0 * inv * k_scale[h * DHD + d0];
        x1 = x1 * inv * k_scale[h * DHD + d0 + 1];
        size_t dst = ((size_t)(b * NH + h) * JTOT + NMEM + n) * DHD + d0;
        g_k[dst] = x0 * cf - x1 * sf;
        g_k[dst + 1] = x1 * cf + x0 * sf;
    }
    {   // v
        size_t dst = ((size_t)(b * NH + h) * JTOT + NMEM + n) * DHD + d0;
        g_v[dst] = g_vraw[src];
        g_v[dst + 1] = g_vraw[src + 1];
    }
}

// ------------- memory kv slots: l2norm(mem_k)*k_scale, copy mem_v -------------
__global__ __launch_bounds__(256) void memprep_k(const float* __restrict__ mem_k,
                                                 const float* __restrict__ mem_v,
                                                 const float* __restrict__ k_scale) {
    int gw = (blockIdx.x * blockDim.x + threadIdx.x) >> 5;
    int lane = threadIdx.x & 31;
    int h = gw / NMEM, m = gw - h * NMEM;
    int d0 = lane * 2;
    float x0 = mem_k[(h * NMEM + m) * DHD + d0];
    float x1 = mem_k[(h * NMEM + m) * DHD + d0 + 1];
    float ss = x0 * x0 + x1 * x1;
#pragma unroll
    for (int o = 16; o; o >>= 1) ss += __shfl_xor_sync(0xffffffffu, ss, o);
    float inv = 1.f / fmaxf(sqrtf(ss), 1e-12f);
    x0 = x0 * inv * k_scale[h * DHD + d0];
    x1 = x1 * inv * k_scale[h * DHD + d0 + 1];
    float v0 = mem_v[(h * NMEM + m) * DHD + d0];
    float v1 = mem_v[(h * NMEM + m) * DHD + d0 + 1];
    for (int b = 0; b < BB; b++) {
        size_t dst = ((size_t)(b * NH + h) * JTOT + m) * DHD + d0;
        g_k[dst] = x0;
        g_k[dst + 1] = x1;
        g_v[dst] = v0;
        g_v[dst + 1] = v1;
    }
}

// --- dots = QKSCALE * q.k: 3xTF32 mma, hi/lo planes precomputed in smem -------
#define DQP 68
__global__ __launch_bounds__(256) void dots_k() {
    int i0 = blockIdx.y * 64;
    int j0 = blockIdx.x * 64;
    if (j0 > i0 + 63 + NMEM) return;
    extern __shared__ float dsm[];
    float* Qh = dsm;
    float* Ql = Qh + 64 * DQP;
    float* Kh = Ql + 64 * DQP;
    float* Kl = Kh + 64 * DQP;
    int bh = blockIdx.z;
    const float* Q = g_q + (size_t)bh * SEQ * DHD;
    const float* K = g_k + (size_t)bh * JTOT * DHD;
    int tid = threadIdx.x;
#pragma unroll
    for (int it = 0; it < 4; it++) {
        int c = tid + it * 256;
        int r = c >> 4, d4 = (c & 15) * 4;
        float4 qv = *reinterpret_cast<const float4*>(&Q[(size_t)(i0 + r) * DHD + d4]);
        unsigned h0, l0, h1, l1, h2, l2, h3, l3;
        tf32pair(qv.x, h0, l0); tf32pair(qv.y, h1, l1);
        tf32pair(qv.z, h2, l2); tf32pair(qv.w, h3, l3);
        *reinterpret_cast<uint4*>(&Qh[r * DQP + d4]) = make_uint4(h0, h1, h2, h3);
        *reinterpret_cast<uint4*>(&Ql[r * DQP + d4]) = make_uint4(l0, l1, l2, l3);
        int jj = j0 + r;
        float4 kv = make_float4(0.f, 0.f, 0.f, 0.f);
        if (jj < JTOT) kv = *reinterpret_cast<const float4*>(&K[(size_t)jj * DHD + d4]);
        tf32pair(kv.x, h0, l0); tf32pair(kv.y, h1, l1);
        tf32pair(kv.z, h2, l2); tf32pair(kv.w, h3, l3);
        *reinterpret_cast<uint4*>(&Kh[r * DQP + d4]) = make_uint4(h0, h1, h2, h3);
        *reinterpret_cast<uint4*>(&Kl[r * DQP + d4]) = make_uint4(l0, l1, l2, l3);
    }
    __syncthreads();
    int w = tid >> 5, lane = tid & 31;
    int wm = (w >> 1) * 16, wn = (w & 1) * 32;
    int qr = lane >> 2, qc = lane & 3;
    float acc[4][4] = {};
#pragma unroll
    for (int kk = 0; kk < 8; kk++) {
        int k = kk * 8 + qc;
        unsigned ah[4], al[4];
        ah[0] = __float_as_uint(Qh[(wm + qr) * DQP + k]);
        ah[1] = __float_as_uint(Qh[(wm + qr + 8) * DQP + k]);
        ah[2] = __float_as_uint(Qh[(wm + qr) * DQP + k + 4]);
        ah[3] = __float_as_uint(Qh[(wm + qr + 8) * DQP + k + 4]);
        al[0] = __float_as_uint(Ql[(wm + qr) * DQP + k]);
        al[1] = __float_as_uint(Ql[(wm + qr + 8) * DQP + k]);
        al[2] = __float_as_uint(Ql[(wm + qr) * DQP + k + 4]);
        al[3] = __float_as_uint(Ql[(wm + qr + 8) * DQP + k + 4]);
#pragma unroll
        for (int ni = 0; ni < 4; ni++) {
            int n = wn + ni * 8 + qr;
            unsigned bh2[2], bl2[2];
            bh2[0] = __float_as_uint(Kh[n * DQP + k]);
            bh2[1] = __float_as_uint(Kh[n * DQP + k + 4]);
            bl2[0] = __float_as_uint(Kl[n * DQP + k]);
            bl2[1] = __float_as_uint(Kl[n * DQP + k + 4]);
            mma_tf32(acc[ni], ah, bh2);
            mma_tf32(acc[ni], ah, bl2);
            mma_tf32(acc[ni], al, bh2);
        }
    }
    float* D = g_dots + (size_t)bh * SEQ * JTOT;
#pragma unroll
    for (int ni = 0; ni < 4; ni++) {
        int i = i0 + wm + qr;
        int j = j0 + wn + ni * 8 + 2 * qc;
        if (j < JTOT) {
            *reinterpret_cast<float2*>(&D[(size_t)i * JTOT + j]) =
                make_float2(acc[ni][0] * QKSCALE, acc[ni][1] * QKSCALE);
            *reinterpret_cast<float2*>(&D[(size_t)(i + 8) * JTOT + j]) =
                make_float2(acc[ni][2] * QKSCALE, acc[ni][3] * QKSCALE);
        }
    }
}

// ------ pre-mix + causal softmax + post-mix, largest-first, band zeros --------
__global__ __launch_bounds__(256) void mixsoft_k(const float* __restrict__ W_pre,
                                                 const float* __restrict__ W_post) {
    extern __shared__ float S[];  // NH * JTOT
    __shared__ float wpre[NH * NH], wpost[NH * NH], inv_l[NH];
    int i = SEQ - 1 - (int)blockIdx.x;  // largest jcnt scheduled first
    int b = blockIdx.y;
    int tid = threadIdx.x;
    wpre[tid] = W_pre[tid];
    wpost[tid] = W_post[tid];
    int jcnt = i + NMEM + 1;
    size_t base = ((size_t)(b * NH) * SEQ + i) * JTOT;
    for (int h = 0; h < NH; h++) {
        size_t off = base + (size_t)h * SEQ * JTOT;
        for (int j = tid; j < jcnt; j += 256) S[h * JTOT + j] = g_dots[off + j];
    }
    __syncthreads();
    for (int j = tid; j < jcnt; j += 256) {
        float sv[NH];
#pragma unroll
        for (int h = 0; h < NH; h++) sv[h] = S[h * JTOT + j];
#pragma unroll
        for (int g = 0; g < NH; g++) {
            float a = 0.f;
#pragma unroll
            for (int h = 0; h < NH; h++) a += wpre[g * NH + h] * sv[h];
            S[g * JTOT + j] = a;
        }
    }
    __syncthreads();
    int w = tid >> 5, lane = tid & 31;
    for (int g = w; g < NH; g += 8) {
        float mx = -3.0e38f;
        for (int j = lane; j < jcnt; j += 32) mx = fmaxf(mx, S[g * JTOT + j]);
#pragma unroll
        for (int o = 16; o; o >>= 1) mx = fmaxf(mx, __shfl_xor_sync(0xffffffffu, mx, o));
        float sum = 0.f;
        for (int j = lane; j < jcnt; j += 32) {
            float e = __expf(S[g * JTOT + j] - mx);
            S[g * JTOT + j] = e;
            sum += e;
        }
#pragma unroll
        for (int o = 16; o; o >>= 1) sum += __shfl_xor_sync(0xffffffffu, sum, o);
        if (lane == 0) inv_l[g] = 1.f / sum;
    }
    __syncthreads();
    for (int j = tid; j < jcnt; j += 256) {
        float pv[NH];
#pragma unroll
        for (int h = 0; h < NH; h++) pv[h] = S[h * JTOT + j] * inv_l[h];
#pragma unroll
        for (int g = 0; g < NH; g++) {
            float a = 0.f;
#pragma unroll
            for (int h = 0; h < NH; h++) a += wpost[g * NH + h] * pv[h];
            g_dots[base + (size_t)g * SEQ * JTOT + j] = a;
        }
    }
    // zero only the band outgemm will read: [jcnt, (i&~63)+80)
    int zend = (i & ~63) + 80;
    if (zend > JTOT) zend = JTOT;
    for (int j = jcnt + tid; j < zend; j += 256) {
#pragma unroll
        for (int g = 0; g < NH; g++) g_dots[base + (size_t)g * SEQ * JTOT + j] = 0.f;
    }
}

// -- out = attn @ v: 2-stage cp.async pipeline, fill-convert hi/lo, + gates ----
#define OPITCH 20
#define VPITCH 17
__global__ __launch_bounds__(256) void outgemm_k(const float* __restrict__ b_h,
                                                 const float* __restrict__ b_v,
                                                 float* __restrict__ outg) {
    __shared__ float Araw[2][64 * OPITCH];  // raw attn staging (cp.async)
    __shared__ float Ah[64 * OPITCH];       // converted hi/lo planes
    __shared__ float Al[64 * OPITCH];
    __shared__ float Vh[64 * VPITCH];       // V^T [d][k] hi/lo
    __shared__ float Vl[64 * VPITCH];
    int bg = blockIdx.y;
    int b = bg >> 4, g = bg & 15;
    int i0 = blockIdx.x * 64;
    const float* Arow = g_dots + (size_t)bg * SEQ * JTOT;
    const float* V = g_v + (size_t)bg * JTOT * DHD;
    int tid = threadIdx.x;
    int w = tid >> 5, lane = tid & 31;
    int wm = (w >> 1) * 16, wn = (w & 1) * 32;
    int qr = lane >> 2, qc = lane & 3;
    int ar = tid >> 2, ac4 = (tid & 3) * 4;   // A fill: row, col*4
    int vk = tid >> 4, vd4 = (tid & 15) * 4;  // V fill: k-row, d*4
    float acc[4][4] = {};
    int kmax = i0 + 80;
    if (kmax > JTOT) kmax = JTOT;
    int KT = kmax >> 4;

    // preload stage 0: A via cp.async, V via register
    cp16(&Araw[0][ar * OPITCH + ac4], &Arow[(size_t)(i0 + ar) * JTOT + ac4]);
    CP_COMMIT;
    float4 vreg = *reinterpret_cast<const float4*>(&V[(size_t)vk * DHD + vd4]);

    for (int kt = 0; kt < KT; kt++) {
        int st = kt & 1;
        int k0n = (kt + 1) << 4;
        if (kt + 1 < KT) {
            cp16(&Araw[st ^ 1][ar * OPITCH + ac4],
                 &Arow[(size_t)(i0 + ar) * JTOT + k0n + ac4]);
            CP_COMMIT;
            CP_WAIT(1);
        } else {
            CP_WAIT(0);
        }
        __syncthreads();  // Araw[st] visible; prior compute done with Ah/Al/Vh/Vl
        // fill-convert A and V into hi/lo planes
        {
            float4 av = *reinterpret_cast<const float4*>(&Araw[st][ar * OPITCH + ac4]);
            unsigned h0, l0, h1, l1, h2, l2, h3, l3;
            tf32pair(av.x, h0, l0); tf32pair(av.y, h1, l1);
            tf32pair(av.z, h2, l2); tf32pair(av.w, h3, l3);
            *reinterpret_cast<uint4*>(&Ah[ar * OPITCH + ac4]) = make_uint4(h0, h1, h2, h3);
            *reinterpret_cast<uint4*>(&Al[ar * OPITCH + ac4]) = make_uint4(l0, l1, l2, l3);
            unsigned vh0, vl0, vh1, vl1, vh2, vl2, vh3, vl3;
            tf32pair(vreg.x, vh0, vl0); tf32pair(vreg.y, vh1, vl1);
            tf32pair(vreg.z, vh2, vl2); tf32pair(vreg.w, vh3, vl3);
            Vh[(vd4 + 0) * VPITCH + vk] = __uint_as_float(vh0);
            Vh[(vd4 + 1) * VPITCH + vk] = __uint_as_float(vh1);
            Vh[(vd4 + 2) * VPITCH + vk] = __uint_as_float(vh2);
            Vh[(vd4 + 3) * VPITCH + vk] = __uint_as_float(vh3);
            Vl[(vd4 + 0) * VPITCH + vk] = __uint_as_float(vl0);
            Vl[(vd4 + 1) * VPITCH + vk] = __uint_as_float(vl1);
            Vl[(vd4 + 2) * VPITCH + vk] = __uint_as_float(vl2);
            Vl[(vd4 + 3) * VPITCH + vk] = __uint_as_float(vl3);
        }
        // prefetch next V tile into registers (overlaps with compute below)
        float4 vnext = vreg;
        if (kt + 1 < KT)
            vnext = *reinterpret_cast<const float4*>(&V[(size_t)(k0n + vk) * DHD + vd4]);
        __syncthreads();
#pragma unroll
        for (int ks = 0; ks < 2; ks++) {
            int k = ks * 8 + qc;
            unsigned ah[4], al[4];
            ah[0] = __float_as_uint(Ah[(wm + qr) * OPITCH + k]);
            ah[1] = __float_as_uint(Ah[(wm + qr + 8) * OPITCH + k]);
            ah[2] = __float_as_uint(Ah[(wm + qr) * OPITCH + k + 4]);
            ah[3] = __float_as_uint(Ah[(wm + qr + 8) * OPITCH + k + 4]);
            al[0] = __float_as_uint(Al[(wm + qr) * OPITCH + k]);
            al[1] = __float_as_uint(Al[(wm + qr + 8) * OPITCH + k]);
            al[2] = __float_as_uint(Al[(wm + qr) * OPITCH + k + 4]);
            al[3] = __float_as_uint(Al[(wm + qr + 8) * OPITCH + k + 4]);
#pragma unroll
            for (int ni = 0; ni < 4; ni++) {
                int n = wn + ni * 8 + qr;
                unsigned bh2[2], bl2[2];
                bh2[0] = __float_as_uint(Vh[n * VPITCH + k]);
                bh2[1] = __float_as_uint(Vh[n * VPITCH + k + 4]);
                bl2[0] = __float_as_uint(Vl[n * VPITCH + k]);
                bl2[1] = __float_as_uint(Vl[n * VPITCH + k + 4]);
                mma_tf32(acc[ni], ah, bh2);
                mma_tf32(acc[ni], ah, bl2);
                mma_tf32(acc[ni], al, bh2);
            }
        }
        vreg = vnext;
    }
    __syncthreads();
#pragma unroll
    for (int rr = 0; rr < 2; rr++) {
        int i = i0 + wm + qr + rr * 8;
        int r = b * SEQ + i;
        float hg = sigm(g_hgate[r * NH + g] + b_h[g]);
#pragma unroll
        for (int ni = 0; ni < 4; ni++) {
            int c = g * DHD + wn + ni * 8 + 2 * qc;
            float2 vgl = *reinterpret_cast<const float2*>(&g_vgate[(size_t)r * DIMM + c]);
            float2 bvl = *reinterpret_cast<const float2*>(&b_v[c]);
            float o0 = acc[ni][rr * 2 + 0] * hg * sigm(vgl.x + bvl.x);
            float o1 = acc[ni][rr * 2 + 1] * hg * sigm(vgl.y + bvl.y);
            *reinterpret_cast<float2*>(&outg[(size_t)r * DIMM + c]) = make_float2(o0, o1);
        }
    }
}

// ------------------------------------------------------------------------------
extern "C" void kernel_launch(void* const* d_in, const int* in_sizes, int n_in,
                              void* d_out, int out_size) {
    const float* x       = (const float*)d_in[0];
    const float* freqs   = (const float*)d_in[1];
    const float* Wq      = (const float*)d_in[2];
    const float* Wk      = (const float*)d_in[3];
    const float* Wv      = (const float*)d_in[4];
    const float* q_scale = (const float*)d_in[5];
    const float* k_scale = (const float*)d_in[6];
    const float* mem_k   = (const float*)d_in[7];
    const float* mem_v   = (const float*)d_in[8];
    const float* W_pre   = (const float*)d_in[9];
    const float* W_post  = (const float*)d_in[10];
    const float* W_hgate = (const float*)d_in[11];
    const float* b_hgate = (const float*)d_in[12];
    const float* W_vgate = (const float*)d_in[13];
    const float* b_vgate = (const float*)d_in[14];
    const float* Wo      = (const float*)d_in[15];
    float* out = (float*)d_out;

    float *qraw, *kraw, *vraw, *vgate, *outg;
    cudaGetSymbolAddress((void**)&qraw, g_qraw);
    cudaGetSymbolAddress((void**)&kraw, g_kraw);
    cudaGetSymbolAddress((void**)&vraw, g_vraw);
    cudaGetSymbolAddress((void**)&vgate, g_vgate);
    cudaGetSymbolAddress((void**)&outg, g_outg);

    // Host-side stream/event objects, created once (no device memory involved;
    // identical launch DAG every call). Never destroyed: destroying a forked
    // stream while its capture is active is illegal.
    static cudaStream_t s1 = nullptr, s2 = nullptr, s3 = nullptr;
    static cudaEvent_t evR = nullptr, evA = nullptr, evB = nullptr, evC = nullptr;
    if (s1 == nullptr) {
        cudaStreamCreateWithFlags(&s1, cudaStreamNonBlocking);
        cudaStreamCreateWithFlags(&s2, cudaStreamNonBlocking);
        cudaStreamCreateWithFlags(&s3, cudaStreamNonBlocking);
        cudaEventCreateWithFlags(&evR, cudaEventDisableTiming);
        cudaEventCreateWithFlags(&evA, cudaEventDisableTiming);
        cudaEventCreateWithFlags(&evB, cudaEventDisableTiming);
        cudaEventCreateWithFlags(&evC, cudaEventDisableTiming);
    }

    dim3 gBig(DIMM / 128, ROWS / 128);  // (8, 32) = 256 blocks

    // fork side streams off the main (captured) stream
    cudaEventRecord(evR, 0);
    cudaStreamWaitEvent(s1, evR, 0);
    cudaStreamWaitEvent(s2, evR, 0);
    cudaStreamWaitEvent(s3, evR, 0);

    // 1) independent front section, 4-way concurrent
    tgemm_k<<<gBig, 256, 0, 0>>>(x, Wq, qraw, ROWS, DIMM, DIMM);         // main
    tgemm_k<<<gBig, 256, 0, s1>>>(x, Wk, kraw, ROWS, DIMM, DIMM);        // s1
    cudaEventRecord(evA, s1);
    memprep_k<<<(NH * NMEM) / 8, 256, 0, s2>>>(mem_k, mem_v, k_scale);   // s2
    tgemm_k<<<gBig, 256, 0, s2>>>(x, Wv, vraw, ROWS, DIMM, DIMM);
    cudaEventRecord(evB, s2);
    tgemm_k<<<gBig, 256, 0, s3>>>(x, W_vgate, vgate, ROWS, DIMM, DIMM);  // s3
    hgate_k<<<ROWS / 8, 256, 0, s3>>>(x, W_hgate);
    cudaEventRecord(evC, s3);

    // join: normrope needs qraw (main) + kraw (s1) + vraw (s2); dots needs memprep (s2)
    cudaStreamWaitEvent(0, evA, 0);
    cudaStreamWaitEvent(0, evB, 0);

    // 2) l2norm + scale + rope + head-major layout
    normrope_k<<<(ROWS * NH) / 8, 256, 0, 0>>>(freqs, q_scale, k_scale);

    // 3) attention scores (3xTF32 mma, hi/lo pre-split in smem, causal tiles)
    {
        int dsmem = 4 * 64 * DQP * (int)sizeof(float);  // 69,632 B
        cudaFuncSetAttribute(dots_k, cudaFuncAttributeMaxDynamicSharedMemorySize, dsmem);
        dots_k<<<dim3((JTOT + 63) / 64, SEQ / 64, BB * NH), 256, dsmem, 0>>>();
    }

    // 4) talking-heads mix + causal softmax + post-mix
    {
        int smem = NH * JTOT * (int)sizeof(float);  // 66,560 B
        cudaFuncSetAttribute(mixsoft_k, cudaFuncAttributeMaxDynamicSharedMemorySize, smem);
        mixsoft_k<<<dim3(SEQ, BB), 256, smem, 0>>>(W_pre, W_post);
    }

    // join vgate/hgate branch before outgemm
    cudaStreamWaitEvent(0, evC, 0);

    // 5) attn @ v (pipelined, 3xTF32 mma) + gates
    outgemm_k<<<dim3(SEQ / 64, BB * NH), 256, 0, 0>>>(b_hgate, b_vgate, outg);

    // 6) output projection
    tgemm_k<<<gBig, 256, 0, 0>>>(outg, Wo, out, ROWS, DIMM, DIMM);
}